// round 9
// baseline (speedup 1.0000x reference)
#include <cuda_runtime.h>
#include <cuda_bf16.h>
#include <math.h>
#include <stdint.h>

#define NROWS 16384
#define MROWS 16384
#define DDIM  512

// ---------------- scratch (no cudaMalloc allowed) ----------------
__device__ __align__(16) signed char g_x1[NROWS * DDIM];  // q1 of x
__device__ __align__(16) signed char g_x2[NROWS * DDIM];  // q2 of x (scale/256)
__device__ __align__(16) signed char g_y1[MROWS * DDIM];
__device__ __align__(16) signed char g_y2[MROWS * DDIM];
__device__ float        g_xsq[NROWS];   // exact fp32 row norms
__device__ float        g_ysq[MROWS];
__device__ float        g_xs[NROWS];    // per-row quant scale
__device__ float        g_ys[MROWS];
__device__ unsigned int g_min[NROWS];

__device__ __forceinline__ uint32_t smem_u32(const void* p) {
    uint32_t a;
    asm("{ .reg .u64 t; cvta.to.shared.u64 t, %1; cvt.u32.u64 %0, t; }"
        : "=r"(a) : "l"(p));
    return a;
}

// ---------------- GEMM config ----------------
#define BK      64                       // int8 k per chunk = 64 B rows
#define NCHUNK  (DDIM / BK)              // 8
#define XTILEB  (128 * 64)               // 8192
#define YTILEB  (64 * 64)                // 4096
#define STAGEB  (2 * XTILEB + 2 * YTILEB) // 24576: X1,X2,Y1,Y2
#define STAGES  4
#define SM_DATA0 1024
#define SM_TOTAL (SM_DATA0 + STAGES * STAGEB)  // 99328 -> 2 CTAs/SM

// 16B-chunk XOR swizzle on 64B rows (conflict-free for cp.async + ldsm)
#define SWZ64(row, col) ((uint32_t)(row) * 64u + \
    ((((uint32_t)(col) >> 4) ^ (((uint32_t)(row) >> 1) & 3u)) << 4) + ((uint32_t)(col) & 15u))

// ---------------------------------------------------------------------------
// Kernel 1: two-term int8 quantization + exact norms + init g_min
// ---------------------------------------------------------------------------
__device__ __forceinline__ uint32_t quant_pack(float4 v, float inv_s, int* q2p) {
    float f[4] = {v.x, v.y, v.z, v.w};
    uint32_t p1 = 0, p2 = 0;
    #pragma unroll
    for (int i = 0; i < 4; i++) {
        float u = f[i] * inv_s;
        int q1 = __float2int_rn(u);
        float r = u - (float)q1;                   // [-0.5, 0.5]
        int q2 = __float2int_rn(256.0f * r);
        q2 = max(-127, min(127, q2));
        p1 |= ((uint32_t)(q1 & 0xff)) << (8 * i);
        p2 |= ((uint32_t)(q2 & 0xff)) << (8 * i);
    }
    *q2p = (int)p2;
    return p1;
}

__global__ void kc_prep_kernel(const float* __restrict__ x,
                               const float* __restrict__ y) {
    int row = blockIdx.x;
    int tid = threadIdx.x;   // 128 threads * 4 = 512
    float4 a = ((const float4*)(x + (size_t)row * DDIM))[tid];
    float4 b = ((const float4*)(y + (size_t)row * DDIM))[tid];

    float amax = fmaxf(fmaxf(fabsf(a.x), fabsf(a.y)), fmaxf(fabsf(a.z), fabsf(a.w)));
    float bmax = fmaxf(fmaxf(fabsf(b.x), fabsf(b.y)), fmaxf(fabsf(b.z), fabsf(b.w)));
    float asum = a.x*a.x + a.y*a.y + a.z*a.z + a.w*a.w;
    float bsum = b.x*b.x + b.y*b.y + b.z*b.z + b.w*b.w;
    #pragma unroll
    for (int o = 16; o > 0; o >>= 1) {
        amax = fmaxf(amax, __shfl_xor_sync(0xffffffffu, amax, o));
        bmax = fmaxf(bmax, __shfl_xor_sync(0xffffffffu, bmax, o));
        asum += __shfl_xor_sync(0xffffffffu, asum, o);
        bsum += __shfl_xor_sync(0xffffffffu, bsum, o);
    }
    __shared__ float sAm[4], sAs[4], sBm[4], sBs[4];
    if ((tid & 31) == 0) {
        sAm[tid >> 5] = amax; sAs[tid >> 5] = asum;
        sBm[tid >> 5] = bmax; sBs[tid >> 5] = bsum;
    }
    __syncthreads();
    float aM = fmaxf(fmaxf(sAm[0], sAm[1]), fmaxf(sAm[2], sAm[3]));
    float bM = fmaxf(fmaxf(sBm[0], sBm[1]), fmaxf(sBm[2], sBm[3]));
    aM = fmaxf(aM, 1e-20f);
    bM = fmaxf(bM, 1e-20f);
    float s_a = aM * (1.0f / 127.0f), inv_a = 127.0f / aM;
    float s_b = bM * (1.0f / 127.0f), inv_b = 127.0f / bM;

    int p2;
    uint32_t p1 = quant_pack(a, inv_a, &p2);
    ((uint32_t*)(g_x1 + (size_t)row * DDIM))[tid] = p1;
    ((uint32_t*)(g_x2 + (size_t)row * DDIM))[tid] = (uint32_t)p2;
    p1 = quant_pack(b, inv_b, &p2);
    ((uint32_t*)(g_y1 + (size_t)row * DDIM))[tid] = p1;
    ((uint32_t*)(g_y2 + (size_t)row * DDIM))[tid] = (uint32_t)p2;

    if (tid == 0) {
        g_xsq[row] = sAs[0] + sAs[1] + sAs[2] + sAs[3];
        g_xs[row]  = s_a;
    }
    if (tid == 1) {
        g_ysq[row] = sBs[0] + sBs[1] + sBs[2] + sBs[3];
        g_ys[row]  = s_b;
    }
    if (tid == 2) g_min[row] = 0x7f800000u;
}

// ---------------------------------------------------------------------------
// cp.async loader: one 64-k chunk (X1,X2: 128x64B, Y1,Y2: 64x64B, swizzled)
// ---------------------------------------------------------------------------
__device__ __forceinline__ void issue_loads(uint32_t stage_smem, int c,
                                            int bm, int bn, int tid) {
    #pragma unroll
    for (int p = 0; p < 2; p++) {
        const char* xb = p ? (const char*)g_x2 : (const char*)g_x1;
        #pragma unroll
        for (int i = 0; i < 2; i++) {
            const int idx = tid + i * 256;       // 0..511
            const int row = idx >> 2;
            const int ch  = (idx & 3) * 16;
            const char* src = xb + (size_t)(bm + row) * DDIM + c * BK + ch;
            const uint32_t dst = stage_smem + p * XTILEB + SWZ64(row, ch);
            asm volatile("cp.async.cg.shared.global [%0], [%1], 16;"
                         :: "r"(dst), "l"(src) : "memory");
        }
    }
    #pragma unroll
    for (int p = 0; p < 2; p++) {
        const char* yb = p ? (const char*)g_y2 : (const char*)g_y1;
        const int row = tid >> 2;                // 0..63
        const int ch  = (tid & 3) * 16;
        const char* src = yb + (size_t)(bn + row) * DDIM + c * BK + ch;
        const uint32_t dst = stage_smem + 2 * XTILEB + p * YTILEB + SWZ64(row, ch);
        asm volatile("cp.async.cg.shared.global [%0], [%1], 16;"
                     :: "r"(dst), "l"(src) : "memory");
    }
    asm volatile("cp.async.commit_group;" ::: "memory");
}

__device__ __forceinline__ void ldsm4(uint32_t* r, uint32_t addr) {
    asm volatile("ldmatrix.sync.aligned.m8n8.x4.shared.b16 {%0,%1,%2,%3}, [%4];"
                 : "=r"(r[0]), "=r"(r[1]), "=r"(r[2]), "=r"(r[3]) : "r"(addr));
}
__device__ __forceinline__ void imma16832(int* d, const uint32_t* a, const uint32_t* b) {
    asm volatile("mma.sync.aligned.m16n8k32.row.col.s32.s8.s8.s32 "
                 "{%0,%1,%2,%3}, {%4,%5,%6,%7}, {%8,%9}, {%0,%1,%2,%3};"
                 : "+r"(d[0]), "+r"(d[1]), "+r"(d[2]), "+r"(d[3])
                 : "r"(a[0]), "r"(a[1]), "r"(a[2]), "r"(a[3]), "r"(b[0]), "r"(b[1]));
}

// ---------------------------------------------------------------------------
// Kernel 2: two-term int8 IMMA GEMM, exact i32 accum, fused row-min
// CTA 128x64, 8 warps (4M x 2N), warp 32x32, 4-stage + 2 CTAs/SM
// dot = sx*sy*(d11 + (d12+d21)/256)
// ---------------------------------------------------------------------------
__global__ void __launch_bounds__(256, 2)
kc_gemm_kernel() {
    extern __shared__ char smem[];
    float*        syn    = (float*)smem;                  // [64] y norms
    float*        sys    = (float*)(smem + 256);          // [64] y scales
    unsigned int* rowmin = (unsigned int*)(smem + 512);   // [128]
    const uint32_t sdata = smem_u32(smem) + SM_DATA0;

    const int tid  = threadIdx.x;
    const int wid  = tid >> 5;
    const int lane = tid & 31;
    const int bm = blockIdx.y * 128;
    const int bn = blockIdx.x * 64;
    const int wm = (wid & 3) * 32;   // 0,32,64,96
    const int wn = (wid >> 2) * 32;  // 0,32

    if (tid < 64)       syn[tid] = g_ysq[bn + tid];
    else if (tid < 128) sys[tid - 64] = g_ys[bn + tid - 64];
    else                rowmin[tid - 128] = 0x7f800000u;

    // per-lane ldmatrix components (16B units over 64B swizzled rows)
    const int arow = ((lane >> 3) & 1) * 8 + (lane & 7);
    const int acol = (lane >> 4) * 16;
    const int brow = (lane >> 4) * 8 + (lane & 7);
    const int bcol = ((lane >> 3) & 1) * 16;

    uint32_t aoff[2][2], boff[2][2];
    #pragma unroll
    for (int kk = 0; kk < 2; kk++) {
        #pragma unroll
        for (int mt = 0; mt < 2; mt++)
            aoff[kk][mt] = SWZ64(wm + mt * 16 + arow, kk * 32 + acol);
        #pragma unroll
        for (int q = 0; q < 2; q++)
            boff[kk][q] = SWZ64(wn + q * 16 + brow, kk * 32 + bcol);
    }

    int acc1[2][4][4], acc2[2][4][4];   // d11 | d12+d21
    #pragma unroll
    for (int mt = 0; mt < 2; mt++)
        #pragma unroll
        for (int nt = 0; nt < 4; nt++)
            #pragma unroll
            for (int e = 0; e < 4; e++) { acc1[mt][nt][e] = 0; acc2[mt][nt][e] = 0; }

    issue_loads(sdata + 0 * STAGEB, 0, bm, bn, tid);
    issue_loads(sdata + 1 * STAGEB, 1, bm, bn, tid);
    issue_loads(sdata + 2 * STAGEB, 2, bm, bn, tid);

    #pragma unroll 1
    for (int c = 0; c < NCHUNK; c++) {
        asm volatile("cp.async.wait_group 2;" ::: "memory");
        __syncthreads();

        if (c + 3 < NCHUNK)
            issue_loads(sdata + ((c + 3) & 3) * STAGEB, c + 3, bm, bn, tid);
        else
            asm volatile("cp.async.commit_group;" ::: "memory");

        const uint32_t st = sdata + (c & 3) * STAGEB;
        const uint32_t X1 = st;
        const uint32_t X2 = st + XTILEB;
        const uint32_t Y1 = st + 2 * XTILEB;
        const uint32_t Y2 = st + 2 * XTILEB + YTILEB;

        #pragma unroll
        for (int kk = 0; kk < 2; kk++) {        // two k32 halves of BK=64
            uint32_t b1f[4][2], b2f[4][2];
            #pragma unroll
            for (int q = 0; q < 2; q++) {
                uint32_t r[4];
                ldsm4(r, Y1 + boff[kk][q]);
                b1f[2*q][0] = r[0]; b1f[2*q][1] = r[1];
                b1f[2*q+1][0] = r[2]; b1f[2*q+1][1] = r[3];
                ldsm4(r, Y2 + boff[kk][q]);
                b2f[2*q][0] = r[0]; b2f[2*q][1] = r[1];
                b2f[2*q+1][0] = r[2]; b2f[2*q+1][1] = r[3];
            }
            #pragma unroll
            for (int mt = 0; mt < 2; mt++) {
                uint32_t a1[4], a2[4];
                ldsm4(a1, X1 + aoff[kk][mt]);
                ldsm4(a2, X2 + aoff[kk][mt]);
                #pragma unroll
                for (int nt = 0; nt < 4; nt++) {
                    imma16832(acc1[mt][nt], a1, b1f[nt]);
                    imma16832(acc2[mt][nt], a1, b2f[nt]);
                    imma16832(acc2[mt][nt], a2, b1f[nt]);
                }
            }
        }
    }
    __syncthreads();

    // epilogue: sq = xsq + ysq - 2*sx*sy*(d11 + cross/256), fused row-min
    #pragma unroll
    for (int mt = 0; mt < 2; mt++) {
        #pragma unroll
        for (int h = 0; h < 2; h++) {
            const int lrow = wm + mt * 16 + (lane >> 2) + h * 8;
            const float xs  = g_xsq[bm + lrow];
            const float sxr = g_xs[bm + lrow];
            float mn = __int_as_float(0x7f800000);
            #pragma unroll
            for (int nt = 0; nt < 4; nt++) {
                #pragma unroll
                for (int e = 0; e < 2; e++) {
                    const int col = wn + nt * 8 + (lane & 3) * 2 + e;
                    float d11 = (float)acc1[mt][nt][h * 2 + e];
                    float dcr = (float)acc2[mt][nt][h * 2 + e];
                    float dot = sxr * sys[col] * fmaf(dcr, 0.00390625f, d11);
                    mn = fminf(mn, fmaf(-2.0f, dot, syn[col]));
                }
            }
            mn = fminf(mn, __shfl_xor_sync(0xffffffffu, mn, 1));
            mn = fminf(mn, __shfl_xor_sync(0xffffffffu, mn, 2));
            if ((lane & 3) == 0) {
                float s = fmaxf(xs + mn, 0.0f);
                atomicMin(&rowmin[lrow], __float_as_uint(s));
            }
        }
    }
    __syncthreads();
    if (tid < 128) atomicMin(&g_min[bm + tid], rowmin[tid]);
}

// ---------------------------------------------------------------------------
// Kernel 3: argmax over min squared distances (tie-break lowest index)
// ---------------------------------------------------------------------------
__global__ void kc_argmax_kernel(float* __restrict__ out) {
    const int tid = threadIdx.x;  // 1024
    unsigned long long best = 0ull;
    for (int i = tid; i < NROWS; i += 1024) {
        unsigned long long key = ((unsigned long long)g_min[i] << 32) |
                                 (unsigned long long)(0xffffffffu - (unsigned)i);
        if (key > best) best = key;
    }
    #pragma unroll
    for (int o = 16; o > 0; o >>= 1) {
        unsigned long long v = __shfl_down_sync(0xffffffffu, best, o);
        if (v > best) best = v;
    }
    __shared__ unsigned long long sh[32];
    if ((tid & 31) == 0) sh[tid >> 5] = best;
    __syncthreads();
    if (tid < 32) {
        best = sh[tid];
        #pragma unroll
        for (int o = 16; o > 0; o >>= 1) {
            unsigned long long v = __shfl_down_sync(0xffffffffu, best, o);
            if (v > best) best = v;
        }
        if (tid == 0) {
            unsigned int vbits = (unsigned int)(best >> 32);
            int idx = (int)(0xffffffffu - (unsigned int)(best & 0xffffffffu));
            out[0] = sqrtf(__uint_as_float(vbits));
            out[1] = (float)idx;
        }
    }
}

// ---------------------------------------------------------------------------
extern "C" void kernel_launch(void* const* d_in, const int* in_sizes, int n_in,
                              void* d_out, int out_size) {
    const float* x = (const float*)d_in[0];
    const float* y = (const float*)d_in[1];
    float* out = (float*)d_out;

    cudaFuncSetAttribute(kc_gemm_kernel,
                         cudaFuncAttributeMaxDynamicSharedMemorySize, SM_TOTAL);

    kc_prep_kernel<<<NROWS, 128>>>(x, y);

    dim3 grid(MROWS / 64, NROWS / 128);   // 256 x 128 CTAs
    kc_gemm_kernel<<<grid, 256, SM_TOTAL>>>();

    kc_argmax_kernel<<<1, 1024>>>(out);
}

// round 10
// speedup vs baseline: 3.0858x; 3.0858x over previous
#include <cuda_runtime.h>
#include <cuda_bf16.h>
#include <math.h>
#include <stdint.h>

#define NROWS 16384
#define MROWS 16384
#define DDIM  512

// ---------------- scratch (no cudaMalloc allowed) ----------------
__device__ __align__(16) __nv_bfloat16 g_xhi[NROWS * DDIM];
__device__ __align__(16) __nv_bfloat16 g_xlo[NROWS * DDIM];
__device__ __align__(16) __nv_bfloat16 g_yhi[MROWS * DDIM];
__device__ __align__(16) __nv_bfloat16 g_ylo[MROWS * DDIM];
__device__ float        g_xsq[NROWS];
__device__ float        g_ysq[MROWS];
__device__ unsigned int g_min[NROWS];

__device__ __forceinline__ uint32_t smem_u32(const void* p) {
    uint32_t a;
    asm("{ .reg .u64 t; cvta.to.shared.u64 t, %1; cvt.u32.u64 %0, t; }"
        : "=r"(a) : "l"(p));
    return a;
}

// ---------------- GEMM config ----------------
#define BK          32                   // bf16 k per chunk = 64 B rows (swizzled)
#define NCHUNK      (DDIM / BK)          // 16
#define ROWB        64                   // native row bytes, XOR-swizzled
#define TILEB       (128 * ROWB)         // 8192
#define STAGEB      (4 * TILEB)          // 32768 (Ahi, Alo, Bhi, Blo)
#define STAGES      3
#define SM_DATA0    1024
#define SM_TOTAL    (SM_DATA0 + STAGES * STAGEB)   // 99328 -> 2 CTAs/SM

// swizzle: 16B chunk index XORed with (row>>1)&3  (conflict-free, 16B aligned)
#define SWZ64(row, col) ((uint32_t)(row) * 64u + \
    ((((uint32_t)(col) >> 4) ^ (((uint32_t)(row) >> 1) & 3u)) << 4) + ((uint32_t)(col) & 15u))

// ---------------------------------------------------------------------------
// Kernel 1: bf16 hi/lo split + squared norms + init g_min
// ---------------------------------------------------------------------------
__global__ void kc_prep_kernel(const float* __restrict__ x,
                               const float* __restrict__ y) {
    int row = blockIdx.x;
    int tid = threadIdx.x;   // 128 threads * 4 elems = 512
    float4 a = ((const float4*)(x + (size_t)row * DDIM))[tid];
    float4 b = ((const float4*)(y + (size_t)row * DDIM))[tid];

    float av[4] = {a.x, a.y, a.z, a.w};
    float bv[4] = {b.x, b.y, b.z, b.w};
    unsigned short ah[4], al[4], bh[4], bl[4];
    float sx = 0.f, sy = 0.f;
    #pragma unroll
    for (int i = 0; i < 4; i++) {
        __nv_bfloat16 h = __float2bfloat16_rn(av[i]);
        ah[i] = __bfloat16_as_ushort(h);
        al[i] = __bfloat16_as_ushort(__float2bfloat16_rn(av[i] - __bfloat162float(h)));
        sx += av[i] * av[i];
        __nv_bfloat16 g = __float2bfloat16_rn(bv[i]);
        bh[i] = __bfloat16_as_ushort(g);
        bl[i] = __bfloat16_as_ushort(__float2bfloat16_rn(bv[i] - __bfloat162float(g)));
        sy += bv[i] * bv[i];
    }
    uint2 u;
    u.x = (uint32_t)ah[0] | ((uint32_t)ah[1] << 16); u.y = (uint32_t)ah[2] | ((uint32_t)ah[3] << 16);
    ((uint2*)(g_xhi + (size_t)row * DDIM))[tid] = u;
    u.x = (uint32_t)al[0] | ((uint32_t)al[1] << 16); u.y = (uint32_t)al[2] | ((uint32_t)al[3] << 16);
    ((uint2*)(g_xlo + (size_t)row * DDIM))[tid] = u;
    u.x = (uint32_t)bh[0] | ((uint32_t)bh[1] << 16); u.y = (uint32_t)bh[2] | ((uint32_t)bh[3] << 16);
    ((uint2*)(g_yhi + (size_t)row * DDIM))[tid] = u;
    u.x = (uint32_t)bl[0] | ((uint32_t)bl[1] << 16); u.y = (uint32_t)bl[2] | ((uint32_t)bl[3] << 16);
    ((uint2*)(g_ylo + (size_t)row * DDIM))[tid] = u;

    #pragma unroll
    for (int o = 16; o > 0; o >>= 1) {
        sx += __shfl_down_sync(0xffffffffu, sx, o);
        sy += __shfl_down_sync(0xffffffffu, sy, o);
    }
    __shared__ float shx[4], shy[4];
    if ((tid & 31) == 0) { shx[tid >> 5] = sx; shy[tid >> 5] = sy; }
    __syncthreads();
    if (tid == 0) g_xsq[row] = shx[0] + shx[1] + shx[2] + shx[3];
    if (tid == 1) g_ysq[row] = shy[0] + shy[1] + shy[2] + shy[3];
    if (tid == 2) g_min[row] = 0x7f800000u;
}

// ---------------------------------------------------------------------------
// cp.async tile loader: one 32-k chunk (4 planes x 128 rows x 64 B, swizzled)
// ---------------------------------------------------------------------------
__device__ __forceinline__ void issue_loads(uint32_t stage_smem, int c,
                                            int bm, int bn, int tid) {
    #pragma unroll
    for (int i = 0; i < 8; i++) {
        const int t = i >> 1;                     // plane id, compile-time
        const int sub = (i & 1) * 256 + tid;      // 0..511 (16B-chunk id in plane)
        const int row = sub >> 2;
        const int ch  = (sub & 3) * 16;
        const char* base = (t == 0) ? (const char*)g_xhi :
                           (t == 1) ? (const char*)g_xlo :
                           (t == 2) ? (const char*)g_yhi : (const char*)g_ylo;
        const int grow = ((t < 2) ? bm : bn) + row;
        const char* src = base + (size_t)grow * (DDIM * 2) + c * (BK * 2) + ch;
        const uint32_t dst = stage_smem + t * TILEB + SWZ64(row, ch);
        asm volatile("cp.async.cg.shared.global [%0], [%1], 16;"
                     :: "r"(dst), "l"(src) : "memory");
    }
    asm volatile("cp.async.commit_group;" ::: "memory");
}

__device__ __forceinline__ void ldsm4(uint32_t* r, uint32_t addr) {
    asm volatile("ldmatrix.sync.aligned.m8n8.x4.shared.b16 {%0,%1,%2,%3}, [%4];"
                 : "=r"(r[0]), "=r"(r[1]), "=r"(r[2]), "=r"(r[3]) : "r"(addr));
}
__device__ __forceinline__ void mma16816(float* d, const uint32_t* a, const uint32_t* b) {
    asm volatile("mma.sync.aligned.m16n8k16.row.col.f32.bf16.bf16.f32 "
                 "{%0,%1,%2,%3}, {%4,%5,%6,%7}, {%8,%9}, {%0,%1,%2,%3};"
                 : "+f"(d[0]), "+f"(d[1]), "+f"(d[2]), "+f"(d[3])
                 : "r"(a[0]), "r"(a[1]), "r"(a[2]), "r"(a[3]), "r"(b[0]), "r"(b[1]));
}

// ---------------------------------------------------------------------------
// Kernel 2: split-bf16 mma.sync GEMM (dot = hihi + hilo + lohi), fused min
// 128x128 CTA, 8 warps (2M x 4N), warp 64x32, 3-stage + 2 CTAs/SM
// B fragments for the whole chunk hoisted right after the barrier
// ---------------------------------------------------------------------------
__global__ void __launch_bounds__(256, 2)
kc_gemm_kernel() {
    extern __shared__ char smem[];
    float*        sy     = (float*)smem;                 // [128]
    unsigned int* rowmin = (unsigned int*)(smem + 512);  // [128]
    const uint32_t sdata = smem_u32(smem) + SM_DATA0;

    const int tid  = threadIdx.x;
    const int wid  = tid >> 5;
    const int lane = tid & 31;
    const int bm = blockIdx.y * 128;
    const int bn = blockIdx.x * 128;
    const int warp_m = (wid >> 2) * 64;   // 0 or 64
    const int warp_n = (wid & 3) * 32;    // 0,32,64,96

    if (tid < 128) sy[tid] = g_ysq[bn + tid];
    else           rowmin[tid - 128] = 0x7f800000u;

    // per-lane ldmatrix row/col components
    const int arow = ((lane >> 3) & 1) * 8 + (lane & 7);
    const int acol = (lane >> 4) * 16;
    const int brow = (lane >> 4) * 8 + (lane & 7);
    const int bcol = ((lane >> 3) & 1) * 16;

    // precomputed swizzled in-plane offsets (loop-invariant)
    uint32_t aoff[2][4], boff[2][2];
    #pragma unroll
    for (int kk = 0; kk < 2; kk++) {
        const int colb = kk * 32;
        #pragma unroll
        for (int mt = 0; mt < 4; mt++)
            aoff[kk][mt] = SWZ64(warp_m + mt * 16 + arow, colb + acol);
        #pragma unroll
        for (int q = 0; q < 2; q++)
            boff[kk][q] = SWZ64(warp_n + q * 16 + brow, colb + bcol);
    }

    float acc[4][4][4];
    #pragma unroll
    for (int mt = 0; mt < 4; mt++)
        #pragma unroll
        for (int nt = 0; nt < 4; nt++)
            #pragma unroll
            for (int e = 0; e < 4; e++) acc[mt][nt][e] = 0.f;

    issue_loads(sdata + 0 * STAGEB, 0, bm, bn, tid);
    issue_loads(sdata + 1 * STAGEB, 1, bm, bn, tid);

    int stage = 0, nstage = 2;
    #pragma unroll 1
    for (int c = 0; c < NCHUNK; c++) {
        asm volatile("cp.async.wait_group 1;" ::: "memory");
        __syncthreads();   // chunk c visible; all warps done with chunk c-1

        if (c + 2 < NCHUNK)
            issue_loads(sdata + nstage * STAGEB, c + 2, bm, bn, tid);
        else
            asm volatile("cp.async.commit_group;" ::: "memory");

        const uint32_t st  = sdata + stage * STAGEB;
        const uint32_t Ahi = st;
        const uint32_t Alo = st + TILEB;
        const uint32_t Bhi = st + 2 * TILEB;
        const uint32_t Blo = st + 3 * TILEB;

        // hoist ALL B fragments for both k16 halves of this chunk
        uint32_t bh[2][4][2], bl[2][4][2];
        #pragma unroll
        for (int kk = 0; kk < 2; kk++) {
            #pragma unroll
            for (int q = 0; q < 2; q++) {
                uint32_t r[4];
                ldsm4(r, Bhi + boff[kk][q]);
                bh[kk][2*q][0] = r[0]; bh[kk][2*q][1] = r[1];
                bh[kk][2*q+1][0] = r[2]; bh[kk][2*q+1][1] = r[3];
                ldsm4(r, Blo + boff[kk][q]);
                bl[kk][2*q][0] = r[0]; bl[kk][2*q][1] = r[1];
                bl[kk][2*q+1][0] = r[2]; bl[kk][2*q+1][1] = r[3];
            }
        }
        #pragma unroll
        for (int kk = 0; kk < 2; kk++) {
            #pragma unroll
            for (int mt = 0; mt < 4; mt++) {
                uint32_t ah[4], al[4];
                ldsm4(ah, Ahi + aoff[kk][mt]);
                ldsm4(al, Alo + aoff[kk][mt]);
                #pragma unroll
                for (int nt = 0; nt < 4; nt++) {
                    mma16816(acc[mt][nt], ah, bh[kk][nt]);
                    mma16816(acc[mt][nt], ah, bl[kk][nt]);
                    mma16816(acc[mt][nt], al, bh[kk][nt]);
                }
            }
        }
        stage = (stage == STAGES - 1) ? 0 : stage + 1;
        nstage = (nstage == STAGES - 1) ? 0 : nstage + 1;
    }
    __syncthreads();

    // epilogue: fused squared-distance row-min
    #pragma unroll
    for (int mt = 0; mt < 4; mt++) {
        #pragma unroll
        for (int h = 0; h < 2; h++) {
            const int lrow = warp_m + mt * 16 + (lane >> 2) + h * 8;
            float mn = __int_as_float(0x7f800000);
            #pragma unroll
            for (int nt = 0; nt < 4; nt++) {
                #pragma unroll
                for (int e = 0; e < 2; e++) {
                    const int col = warp_n + nt * 8 + (lane & 3) * 2 + e;
                    mn = fminf(mn, fmaf(-2.0f, acc[mt][nt][h * 2 + e], sy[col]));
                }
            }
            mn = fminf(mn, __shfl_xor_sync(0xffffffffu, mn, 1));
            mn = fminf(mn, __shfl_xor_sync(0xffffffffu, mn, 2));
            if ((lane & 3) == 0) {
                float s = fmaxf(g_xsq[bm + lrow] + mn, 0.0f);
                atomicMin(&rowmin[lrow], __float_as_uint(s));
            }
        }
    }
    __syncthreads();
    if (tid < 128) atomicMin(&g_min[bm + tid], rowmin[tid]);
}

// ---------------------------------------------------------------------------
// Kernel 3: argmax over min squared distances (tie-break lowest index)
// ---------------------------------------------------------------------------
__global__ void kc_argmax_kernel(float* __restrict__ out) {
    const int tid = threadIdx.x;  // 1024
    unsigned long long best = 0ull;
    for (int i = tid; i < NROWS; i += 1024) {
        unsigned long long key = ((unsigned long long)g_min[i] << 32) |
                                 (unsigned long long)(0xffffffffu - (unsigned)i);
        if (key > best) best = key;
    }
    #pragma unroll
    for (int o = 16; o > 0; o >>= 1) {
        unsigned long long v = __shfl_down_sync(0xffffffffu, best, o);
        if (v > best) best = v;
    }
    __shared__ unsigned long long sh[32];
    if ((tid & 31) == 0) sh[tid >> 5] = best;
    __syncthreads();
    if (tid < 32) {
        best = sh[tid];
        #pragma unroll
        for (int o = 16; o > 0; o >>= 1) {
            unsigned long long v = __shfl_down_sync(0xffffffffu, best, o);
            if (v > best) best = v;
        }
        if (tid == 0) {
            unsigned int vbits = (unsigned int)(best >> 32);
            int idx = (int)(0xffffffffu - (unsigned int)(best & 0xffffffffu));
            out[0] = sqrtf(__uint_as_float(vbits));
            out[1] = (float)idx;
        }
    }
}

// ---------------------------------------------------------------------------
extern "C" void kernel_launch(void* const* d_in, const int* in_sizes, int n_in,
                              void* d_out, int out_size) {
    const float* x = (const float*)d_in[0];
    const float* y = (const float*)d_in[1];
    float* out = (float*)d_out;

    cudaFuncSetAttribute(kc_gemm_kernel,
                         cudaFuncAttributeMaxDynamicSharedMemorySize, SM_TOTAL);

    kc_prep_kernel<<<NROWS, 128>>>(x, y);

    dim3 grid(MROWS / 128, NROWS / 128);
    kc_gemm_kernel<<<grid, 256, SM_TOTAL>>>();

    kc_argmax_kernel<<<1, 1024>>>(out);
}